// round 10
// baseline (speedup 1.0000x reference)
#include <cuda_runtime.h>
#include <cuda_bf16.h>

// GraphAddPooling: out[g] = sum_{i: batch[i]==g} x[i]
// x: [200000, 256] fp32, batch: sorted (int32/int64, detected), out: [512,256] fp32.
//
// Single kernel, no atomics, no zeroing, no cross-block sync.
// One block per (segment, column half): 1024 blocks x 256 threads.
//   - seeded warp k-ary lower_bound: window E +/- 1500 (validity probes issued
//     concurrently with round-1 partition probes; full-search fallback)
//   - 8 row-streams x 32 float4-lanes (512B per warp, coalesced), DEPTH-5
//     prefetch (only change vs the confirmed 35.5us/74.5%-DRAM R9 engine:
//     one more rotation buffer -> steady-state MLP 4->5; 36 regs, still
//     7 CTAs/SM, single wave)
//   - smem combine, unconditional plain store (covers empty segments)

#define NCOLS   256
#define VCOLS   64      // float4 per full row
#define LANES   32      // float4 lanes per column half (128 cols = 512B)
#define STREAMS 8
#define TPB     256
#define SEED_M  1500    // half-window for seeded search (6.7 sigma)

// Plain k-ary lower_bound rounds on [lo, lo+rem).
__device__ __forceinline__ long klb_rounds(const int* __restrict__ b, int shift,
                                           long lo, long rem, int target, int lane) {
    while (rem > 0) {
        long chunk = (rem + 32) / 33;
        long p = lo + chunk * (lane + 1) - 1;
        bool lt = false;
        if (p < lo + rem) lt = (b[p << shift] < target);
        unsigned m = __ballot_sync(0xffffffffu, lt);
        int k = __popc(m);
        lo += (long)k * chunk;
        long r2 = rem - (long)k * chunk;
        rem = (r2 <= 0) ? 0 : ((r2 >= chunk) ? (chunk - 1) : r2);
    }
    return lo;
}

// Seeded lower_bound: round-1 partition probes + window-validity probes are
// independent loads issued together (one memory round), then 2 more rounds.
__device__ __forceinline__ int seeded_lower_bound(const int* __restrict__ b,
                                                  int shift, int n, int nseg,
                                                  int target, int lane) {
    long E = (long)target * n / nseg;
    long lo0 = E - SEED_M; if (lo0 < 0) lo0 = 0;
    long hi0 = E + SEED_M; if (hi0 > n) hi0 = n;
    long rem0 = hi0 - lo0;

    long chunk = (rem0 + 32) / 33;
    long p = lo0 + chunk * (lane + 1) - 1;
    bool lt = false;
    if (p < hi0) lt = (b[p << shift] < target);
    // validity probes (independent of partition probes; broadcast loads)
    bool vlo = (lo0 == 0) || (b[(lo0 - 1) << shift] < target);
    bool vhi = (hi0 == n) || (b[(hi0 - 1) << shift] >= target);
    unsigned m = __ballot_sync(0xffffffffu, lt);

    if (vlo && vhi) {
        int k = __popc(m);
        long lo = lo0 + (long)k * chunk;
        long r2 = rem0 - (long)k * chunk;
        long rem = (r2 <= 0) ? 0 : ((r2 >= chunk) ? (chunk - 1) : r2);
        return (int)klb_rounds(b, shift, lo, rem, target, lane);
    }
    // window missed (never for this data; guaranteed-correct fallback)
    return (int)klb_rounds(b, shift, 0, n, target, lane);
}

__global__ __launch_bounds__(TPB, 7) void gap_seg_kernel(
    const float4* __restrict__ x,
    const int* __restrict__ b32,     // batch viewed as int32 words
    float4* __restrict__ out,
    int nrows, int nseg)
{
    __shared__ int    s_bounds[2];
    __shared__ float4 s_part[STREAMS][LANES];

    const int g    = blockIdx.x >> 1;        // segment
    const int ch   = blockIdx.x & 1;         // column half
    const int tid  = threadIdx.x;
    const int lane = tid & (LANES - 1);      // float4 lane within half
    const int ys   = tid >> 5;               // row stream 0..7 (== warp id)

    // int64 vs int32 batch: sorted ids < nseg, so little-endian int64 puts a
    // zero high word at int32 index nrows-1.
    const int shift = (b32[nrows - 1] == 0) ? 1 : 0;

    if (ys < 2) {
        int r = seeded_lower_bound(b32, shift, nrows, nseg, g + ys, lane);
        if (lane == 0) s_bounds[ys] = r;
    }
    __syncthreads();
    const int lo = s_bounds[0];
    const int hi = s_bounds[1];

    const float4* xq = x + (size_t)ch * LANES + lane;   // column offset

    // Depth-5 pipelined stream over rows lo+ys, lo+ys+8, ...
    float4 acc = make_float4(0.f, 0.f, 0.f, 0.f);
    int r = lo + ys;

    float4 va = make_float4(0.f, 0.f, 0.f, 0.f);
    float4 vb = make_float4(0.f, 0.f, 0.f, 0.f);
    float4 vc = make_float4(0.f, 0.f, 0.f, 0.f);
    float4 vd = make_float4(0.f, 0.f, 0.f, 0.f);
    if (r < hi)                va = xq[(size_t)r * VCOLS];
    if (r + STREAMS < hi)      vb = xq[(size_t)(r + STREAMS) * VCOLS];
    if (r + 2 * STREAMS < hi)  vc = xq[(size_t)(r + 2 * STREAMS) * VCOLS];
    if (r + 3 * STREAMS < hi)  vd = xq[(size_t)(r + 3 * STREAMS) * VCOLS];

    for (; r < hi; r += STREAMS) {
        float4 ve = make_float4(0.f, 0.f, 0.f, 0.f);
        if (r + 4 * STREAMS < hi) ve = xq[(size_t)(r + 4 * STREAMS) * VCOLS];
        acc.x += va.x; acc.y += va.y; acc.z += va.z; acc.w += va.w;
        va = vb; vb = vc; vc = vd; vd = ve;
    }

    s_part[ys][lane] = acc;
    __syncthreads();

    if (tid < LANES) {
        float4 a = s_part[0][tid];
        #pragma unroll
        for (int s = 1; s < STREAMS; s++) {
            float4 b = s_part[s][tid];
            a.x += b.x; a.y += b.y; a.z += b.z; a.w += b.w;
        }
        // Disjoint (segment, half) output -> unconditional plain store
        // (also initializes empty segments over the poisoned buffer).
        out[(size_t)g * VCOLS + ch * LANES + tid] = a;
    }
}

extern "C" void kernel_launch(void* const* d_in, const int* in_sizes, int n_in,
                              void* d_out, int out_size) {
    const float4* x  = (const float4*)d_in[0];
    const int* batch = (const int*)d_in[1];
    float4* out      = (float4*)d_out;

    const int nrows = in_sizes[1];        // 200000
    const int nseg  = out_size / NCOLS;   // 512

    gap_seg_kernel<<<nseg * 2, TPB>>>(x, batch, out, nrows, nseg);
}

// round 11
// speedup vs baseline: 1.0113x; 1.0113x over previous
#include <cuda_runtime.h>
#include <cuda_bf16.h>

// GraphAddPooling: out[g] = sum_{i: batch[i]==g} x[i]
// x: [200000, 256] fp32, batch: sorted (int32/int64, detected), out: [512,256] fp32.
//
// FINAL (R6/R9 engine, reproduced twice at 35.5us kernel / 74.5% DRAM,
// 5.9 TB/s ~ 86% of the B300 path-independent LTS streaming cap).
//
// Single kernel, no atomics, no zeroing, no cross-block sync.
// One block per (segment, column half): 1024 blocks x 256 threads.
//   - seeded warp k-ary lower_bound: window E +/- 1500 (validity probes issued
//     concurrently with round-1 partition probes; guaranteed-correct
//     full-search fallback) -> 3 dependent probe rounds, mostly L2-warm
//   - 8 row-streams x 32 float4-lanes (512B per warp, coalesced), depth-4
//     prefetch, plain loads
//   - smem combine, unconditional plain store (covers empty segments over
//     the poisoned output buffer)
//
// Ruled out by measurement: in-kernel sync fusion (-4..-12us), warp-autonomous
// restructuring (-0.4us), hand-unrolled steady loops (-6us), depth-5 (+-0),
// __ldcs, column-quarter grids, per-row atomics.

#define NCOLS   256
#define VCOLS   64      // float4 per full row
#define LANES   32      // float4 lanes per column half (128 cols = 512B)
#define STREAMS 8
#define TPB     256
#define SEED_M  1500    // half-window for seeded search (6.7 sigma)

// Plain k-ary lower_bound rounds on [lo, lo+rem).
__device__ __forceinline__ long klb_rounds(const int* __restrict__ b, int shift,
                                           long lo, long rem, int target, int lane) {
    while (rem > 0) {
        long chunk = (rem + 32) / 33;
        long p = lo + chunk * (lane + 1) - 1;
        bool lt = false;
        if (p < lo + rem) lt = (b[p << shift] < target);
        unsigned m = __ballot_sync(0xffffffffu, lt);
        int k = __popc(m);
        lo += (long)k * chunk;
        long r2 = rem - (long)k * chunk;
        rem = (r2 <= 0) ? 0 : ((r2 >= chunk) ? (chunk - 1) : r2);
    }
    return lo;
}

// Seeded lower_bound: round-1 partition probes + window-validity probes are
// independent loads issued together (one memory round), then 2 more rounds.
__device__ __forceinline__ int seeded_lower_bound(const int* __restrict__ b,
                                                  int shift, int n, int nseg,
                                                  int target, int lane) {
    long E = (long)target * n / nseg;
    long lo0 = E - SEED_M; if (lo0 < 0) lo0 = 0;
    long hi0 = E + SEED_M; if (hi0 > n) hi0 = n;
    long rem0 = hi0 - lo0;

    long chunk = (rem0 + 32) / 33;
    long p = lo0 + chunk * (lane + 1) - 1;
    bool lt = false;
    if (p < hi0) lt = (b[p << shift] < target);
    // validity probes (independent of partition probes; broadcast loads)
    bool vlo = (lo0 == 0) || (b[(lo0 - 1) << shift] < target);
    bool vhi = (hi0 == n) || (b[(hi0 - 1) << shift] >= target);
    unsigned m = __ballot_sync(0xffffffffu, lt);

    if (vlo && vhi) {
        int k = __popc(m);
        long lo = lo0 + (long)k * chunk;
        long r2 = rem0 - (long)k * chunk;
        long rem = (r2 <= 0) ? 0 : ((r2 >= chunk) ? (chunk - 1) : r2);
        return (int)klb_rounds(b, shift, lo, rem, target, lane);
    }
    // window missed (never for this data; guaranteed-correct fallback)
    return (int)klb_rounds(b, shift, 0, n, target, lane);
}

__global__ __launch_bounds__(TPB, 7) void gap_seg_kernel(
    const float4* __restrict__ x,
    const int* __restrict__ b32,     // batch viewed as int32 words
    float4* __restrict__ out,
    int nrows, int nseg)
{
    __shared__ int    s_bounds[2];
    __shared__ float4 s_part[STREAMS][LANES];

    const int g    = blockIdx.x >> 1;        // segment
    const int ch   = blockIdx.x & 1;         // column half
    const int tid  = threadIdx.x;
    const int lane = tid & (LANES - 1);      // float4 lane within half
    const int ys   = tid >> 5;               // row stream 0..7 (== warp id)

    // int64 vs int32 batch: sorted ids < nseg, so little-endian int64 puts a
    // zero high word at int32 index nrows-1.
    const int shift = (b32[nrows - 1] == 0) ? 1 : 0;

    if (ys < 2) {
        int r = seeded_lower_bound(b32, shift, nrows, nseg, g + ys, lane);
        if (lane == 0) s_bounds[ys] = r;
    }
    __syncthreads();
    const int lo = s_bounds[0];
    const int hi = s_bounds[1];

    const float4* xq = x + (size_t)ch * LANES + lane;   // column offset

    // Depth-4 pipelined stream over rows lo+ys, lo+ys+8, ...
    float4 acc = make_float4(0.f, 0.f, 0.f, 0.f);
    int r = lo + ys;

    float4 va = make_float4(0.f, 0.f, 0.f, 0.f);
    float4 vb = make_float4(0.f, 0.f, 0.f, 0.f);
    float4 vc = make_float4(0.f, 0.f, 0.f, 0.f);
    if (r < hi)                va = xq[(size_t)r * VCOLS];
    if (r + STREAMS < hi)      vb = xq[(size_t)(r + STREAMS) * VCOLS];
    if (r + 2 * STREAMS < hi)  vc = xq[(size_t)(r + 2 * STREAMS) * VCOLS];

    for (; r < hi; r += STREAMS) {
        float4 vd = make_float4(0.f, 0.f, 0.f, 0.f);
        if (r + 3 * STREAMS < hi) vd = xq[(size_t)(r + 3 * STREAMS) * VCOLS];
        acc.x += va.x; acc.y += va.y; acc.z += va.z; acc.w += va.w;
        va = vb; vb = vc; vc = vd;
    }

    s_part[ys][lane] = acc;
    __syncthreads();

    if (tid < LANES) {
        float4 a = s_part[0][tid];
        #pragma unroll
        for (int s = 1; s < STREAMS; s++) {
            float4 b = s_part[s][tid];
            a.x += b.x; a.y += b.y; a.z += b.z; a.w += b.w;
        }
        // Disjoint (segment, half) output -> unconditional plain store
        // (also initializes empty segments over the poisoned buffer).
        out[(size_t)g * VCOLS + ch * LANES + tid] = a;
    }
}

extern "C" void kernel_launch(void* const* d_in, const int* in_sizes, int n_in,
                              void* d_out, int out_size) {
    const float4* x  = (const float4*)d_in[0];
    const int* batch = (const int*)d_in[1];
    float4* out      = (float4*)d_out;

    const int nrows = in_sizes[1];        // 200000
    const int nseg  = out_size / NCOLS;   // 512

    gap_seg_kernel<<<nseg * 2, TPB>>>(x, batch, out, nrows, nseg);
}